// round 3
// baseline (speedup 1.0000x reference)
#include <cuda_runtime.h>
#include <math.h>

#define NB 32
#define NC 256
#define NK 64
#define NHW 4096
#define NIN 320
#define BN_EPS 1e-5f

// ---------------- scratch (static device global; no allocation at runtime) ----
#define OFF_CORR 0L                       // 32*64*4096
#define OFF_DW   8388608L                 // 32*320*4096
#define OFF_S    50331648L                // 32*256*4096
#define OFF_PX   83886080L                // 32*256*4096
#define OFF_G    117440512L               // 32*256*256
#define OFF_T1   119537664L
#define OFF_ATT  121634816L
#define OFF_T2   123731968L
#define OFF_M    125829120L
#define OFF_R    127926272L               // 32*256
#define OFF_U    127934464L
#define OFF_W    127942656L
#define OFF_CV   127950848L
#define SCRATCH_FLOATS 127959040L

__device__ float g_scratch[SCRATCH_FLOATS];

// ---------------- packed f32x2 helpers (ptxas will NOT auto-fuse; PTX only) --
__device__ __forceinline__ unsigned long long pack2(float lo, float hi) {
    unsigned long long r;
    asm("mov.b64 %0, {%1, %2};" : "=l"(r) : "f"(lo), "f"(hi));
    return r;
}
__device__ __forceinline__ void unpack2(unsigned long long v, float& lo, float& hi) {
    asm("mov.b64 {%0, %1}, %2;" : "=f"(lo), "=f"(hi) : "l"(v));
}
#define FFMA2(d, a, b) asm("fma.rn.f32x2 %0, %1, %2, %0;" : "+l"(d) : "l"(a), "l"(b))

// =============================================================================
// Big GEMM: 128x128 block tile, BK=8, 8x8 per thread (packed 4x8 f32x2), 256 thr.
// A row-major [M,K]. BMODE: 0 = B row-major [K,N]; 1 = B is [N,K] (B^T).
// EPI: 0 none | 1 +bias(p0[m]) | 2 bias+BN+ReLU | 4 final (+cvec +s)
// SPLIT: K-split factor; if >1 epilogue is atomicAdd (C must be zeroed first).
// =============================================================================
template<int BMODE, int EPI, int SPLIT>
__global__ __launch_bounds__(256) void gemm128_k(
    const float* __restrict__ A, const float* __restrict__ Bm, float* __restrict__ Cm,
    int M, int N, int Kd, long aBS, long bBS, long cBS,
    const float* __restrict__ p0, const float* __restrict__ p1,
    const float* __restrict__ p2, const float* __restrict__ p3,
    const float* __restrict__ p4)
{
    __shared__ float As[8][132];
    __shared__ float Bs[8][132];
    const int b  = blockIdx.z / SPLIT;
    const int ks = blockIdx.z % SPLIT;
    const int KC = Kd / SPLIT;
    const float* Ab = A  + (long)b * aBS;
    const float* Bb = Bm + (long)b * bBS;
    float* Cb = Cm + (long)b * cBS;
    const int n0 = blockIdx.x * 128;
    const int m0 = blockIdx.y * 128;
    const int t  = threadIdx.x;
    const int tx = t & 15, ty = t >> 4;

    // acc2[ih][j]: lo = row 2*ih, hi = row 2*ih+1 of the 8x8 micro-tile
    unsigned long long acc2[4][8];
    #pragma unroll
    for (int i = 0; i < 4; i++)
        #pragma unroll
        for (int j = 0; j < 8; j++) acc2[i][j] = 0ull;

    const int arow = t >> 1, akq = (t & 1) * 4;
    const int kend = (ks + 1) * KC;
    for (int k0 = ks * KC; k0 < kend; k0 += 8) {
        // ---- stage A tile: As[kk][m] ----
        {
            float4 va = *reinterpret_cast<const float4*>(&Ab[(long)(m0 + arow) * Kd + k0 + akq]);
            As[akq + 0][arow] = va.x; As[akq + 1][arow] = va.y;
            As[akq + 2][arow] = va.z; As[akq + 3][arow] = va.w;
        }
        // ---- stage B tile: Bs[kk][n] ----
        if (BMODE == 0) {
            int kk = t >> 5, nq = (t & 31) * 4;
            float4 vb = *reinterpret_cast<const float4*>(&Bb[(long)(k0 + kk) * N + n0 + nq]);
            *reinterpret_cast<float4*>(&Bs[kk][nq]) = vb;
        } else {
            int n = t >> 1, kq = (t & 1) * 4;
            float4 vb = *reinterpret_cast<const float4*>(&Bb[(long)(n0 + n) * Kd + k0 + kq]);
            Bs[kq + 0][n] = vb.x; Bs[kq + 1][n] = vb.y;
            Bs[kq + 2][n] = vb.z; Bs[kq + 3][n] = vb.w;
        }
        __syncthreads();

        #pragma unroll
        for (int kk = 0; kk < 8; kk++) {
            // A pairs come packed for free from the vector LDS
            ulonglong2 au0 = *reinterpret_cast<const ulonglong2*>(&As[kk][ty * 8]);
            ulonglong2 au1 = *reinterpret_cast<const ulonglong2*>(&As[kk][ty * 8 + 4]);
            unsigned long long au[4] = {au0.x, au0.y, au1.x, au1.y};
            float4 b0 = *reinterpret_cast<const float4*>(&Bs[kk][tx * 8]);
            float4 b1 = *reinterpret_cast<const float4*>(&Bs[kk][tx * 8 + 4]);
            unsigned long long bd[8];
            bd[0] = pack2(b0.x, b0.x); bd[1] = pack2(b0.y, b0.y);
            bd[2] = pack2(b0.z, b0.z); bd[3] = pack2(b0.w, b0.w);
            bd[4] = pack2(b1.x, b1.x); bd[5] = pack2(b1.y, b1.y);
            bd[6] = pack2(b1.z, b1.z); bd[7] = pack2(b1.w, b1.w);
            #pragma unroll
            for (int i = 0; i < 4; i++)
                #pragma unroll
                for (int j = 0; j < 8; j++)
                    FFMA2(acc2[i][j], au[i], bd[j]);
        }
        __syncthreads();
    }

    // ---- epilogue ----
    #pragma unroll
    for (int ih = 0; ih < 4; ih++) {
        float vlo[8], vhi[8];
        #pragma unroll
        for (int j = 0; j < 8; j++) unpack2(acc2[ih][j], vlo[j], vhi[j]);
        const int mlo = m0 + ty * 8 + 2 * ih;
        const int mhi = mlo + 1;
        if (SPLIT > 1) {
            #pragma unroll
            for (int j = 0; j < 8; j++) {
                int n = n0 + tx * 8 + j;
                atomicAdd(&Cb[(long)mlo * N + n], vlo[j]);
                atomicAdd(&Cb[(long)mhi * N + n], vhi[j]);
            }
        } else {
            #pragma unroll
            for (int half = 0; half < 2; half++) {
                const int m = half ? mhi : mlo;
                float* vv = half ? vhi : vlo;
                if (EPI == 1) {
                    float bias = p0[m];
                    #pragma unroll
                    for (int j = 0; j < 8; j++) vv[j] += bias;
                } else if (EPI == 2) {
                    float bias  = p0[m];
                    float scale = rsqrtf(p2[m] + BN_EPS) * p3[m];
                    float mean  = p1[m], beta = p4[m];
                    #pragma unroll
                    for (int j = 0; j < 8; j++) {
                        float xx = vv[j] + bias;
                        xx = (xx - mean) * scale + beta;
                        vv[j] = fmaxf(xx, 0.0f);
                    }
                } else if (EPI == 4) {
                    float cv = p0[b * NC + m];
                    const float* srow = &p1[(long)b * cBS + (long)m * N + n0 + tx * 8];
                    float4 s0 = *reinterpret_cast<const float4*>(srow);
                    float4 s1 = *reinterpret_cast<const float4*>(srow + 4);
                    vv[0] += cv + s0.x; vv[1] += cv + s0.y;
                    vv[2] += cv + s0.z; vv[3] += cv + s0.w;
                    vv[4] += cv + s1.x; vv[5] += cv + s1.y;
                    vv[6] += cv + s1.z; vv[7] += cv + s1.w;
                }
                *reinterpret_cast<float4*>(&Cb[(long)m * N + n0 + tx * 8]) =
                    make_float4(vv[0], vv[1], vv[2], vv[3]);
                *reinterpret_cast<float4*>(&Cb[(long)m * N + n0 + tx * 8 + 4]) =
                    make_float4(vv[4], vv[5], vv[6], vv[7]);
            }
        }
    }
}

__global__ void zero_k(float* __restrict__ p, long n)
{
    long i = (long)blockIdx.x * blockDim.x + threadIdx.x;
    if (i < n) p[i] = 0.0f;
}

// =============================================================================
// Small GEMM: 64x64 tile, 4x4/thread (packed 2x4 f32x2)
// AM: 0 = A row-major [M,K]; 1 = A^T.  BM: 0 = B row-major; 1 = B^T.
// EPI: 0 none | 3 score epilogue
// =============================================================================
template<int AM, int BM, int EPI>
__global__ __launch_bounds__(256) void gemm_k(
    const float* __restrict__ A, const float* __restrict__ Bm, float* __restrict__ Cm,
    int M, int N, int Kd, long aBS, long bBS, long cBS,
    const float* __restrict__ p0, const float* __restrict__ p1,
    const float* __restrict__ p2, const float* __restrict__ p3)
{
    __shared__ float As[16][64];
    __shared__ float Bs[16][64];
    const int b = blockIdx.z;
    const float* Ab = A + (long)b * aBS;
    const float* Bb = Bm + (long)b * bBS;
    float* Cb = Cm + (long)b * cBS;
    const int n0 = blockIdx.x * 64;
    const int m0 = blockIdx.y * 64;
    const int t  = threadIdx.x;
    const int tx = t & 15, ty = t >> 4;

    unsigned long long acc2[2][4];
    #pragma unroll
    for (int i = 0; i < 2; i++)
        #pragma unroll
        for (int j = 0; j < 4; j++) acc2[i][j] = 0ull;

    for (int k0 = 0; k0 < Kd; k0 += 16) {
        if (AM == 0) {
            int m = t >> 2, kq = (t & 3) * 4;
            float4 va = *reinterpret_cast<const float4*>(&Ab[(long)(m0 + m) * Kd + k0 + kq]);
            As[kq + 0][m] = va.x; As[kq + 1][m] = va.y;
            As[kq + 2][m] = va.z; As[kq + 3][m] = va.w;
        } else {
            int kk = t >> 4, mq = (t & 15) * 4;
            float4 va = *reinterpret_cast<const float4*>(&Ab[(long)(k0 + kk) * M + m0 + mq]);
            *reinterpret_cast<float4*>(&As[kk][mq]) = va;
        }
        if (BM == 0) {
            int kk = t >> 4, nq = (t & 15) * 4;
            float4 vb = *reinterpret_cast<const float4*>(&Bb[(long)(k0 + kk) * N + n0 + nq]);
            *reinterpret_cast<float4*>(&Bs[kk][nq]) = vb;
        } else {
            int n = t >> 2, kq = (t & 3) * 4;
            float4 vb = *reinterpret_cast<const float4*>(&Bb[(long)(n0 + n) * Kd + k0 + kq]);
            Bs[kq + 0][n] = vb.x; Bs[kq + 1][n] = vb.y;
            Bs[kq + 2][n] = vb.z; Bs[kq + 3][n] = vb.w;
        }
        __syncthreads();

        #pragma unroll
        for (int kk = 0; kk < 16; kk++) {
            ulonglong2 auv = *reinterpret_cast<const ulonglong2*>(&As[kk][ty * 4]);
            unsigned long long au[2] = {auv.x, auv.y};
            float4 bf = *reinterpret_cast<const float4*>(&Bs[kk][tx * 4]);
            unsigned long long bd[4];
            bd[0] = pack2(bf.x, bf.x); bd[1] = pack2(bf.y, bf.y);
            bd[2] = pack2(bf.z, bf.z); bd[3] = pack2(bf.w, bf.w);
            #pragma unroll
            for (int i = 0; i < 2; i++)
                #pragma unroll
                for (int j = 0; j < 4; j++)
                    FFMA2(acc2[i][j], au[i], bd[j]);
        }
        __syncthreads();
    }

    #pragma unroll
    for (int ih = 0; ih < 2; ih++) {
        float vlo[4], vhi[4];
        #pragma unroll
        for (int j = 0; j < 4; j++) unpack2(acc2[ih][j], vlo[j], vhi[j]);
        #pragma unroll
        for (int half = 0; half < 2; half++) {
            const int m = m0 + ty * 4 + 2 * ih + half;
            float* vv = half ? vhi : vlo;
            if (EPI == 3) {
                float u  = p0[b * NC + m];
                float bq = p2[m];
                #pragma unroll
                for (int j = 0; j < 4; j++) {
                    int n = n0 + tx * 4 + j;
                    float bk = p1[n];
                    float w  = p3[b * NC + n];
                    vv[j] = (vv[j] + u * bk + bq * w + 4096.0f * bq * bk) * 0.0625f;
                }
            }
            *reinterpret_cast<float4*>(&Cb[(long)m * N + n0 + tx * 4]) =
                make_float4(vv[0], vv[1], vv[2], vv[3]);
        }
    }
}

// =============================================================================
// Depthwise 3x3 (pad 1) over concat([corr(64ch), d(256ch)])
// =============================================================================
__global__ __launch_bounds__(256) void dw_k(
    const float* __restrict__ corr, const float* __restrict__ dten,
    const float* __restrict__ w, const float* __restrict__ bias,
    float* __restrict__ out)
{
    const int bc = blockIdx.x;
    const int b = bc / NIN, ch = bc % NIN;
    const float* src = (ch < NK) ? (corr + ((long)b * NK + ch) * NHW)
                                 : (dten + ((long)b * NC + (ch - NK)) * NHW);
    __shared__ float tile[66][66];
    const int t = threadIdx.x;
    for (int idx = t; idx < 66 * 66; idx += 256) {
        int yy = idx / 66, xx = idx % 66;
        int y = yy - 1, x = xx - 1;
        float v = 0.0f;
        if (y >= 0 && y < 64 && x >= 0 && x < 64) v = src[y * 64 + x];
        tile[yy][xx] = v;
    }
    __syncthreads();

    float wk[9];
    #pragma unroll
    for (int i = 0; i < 9; i++) wk[i] = w[ch * 9 + i];
    const float bb = bias[ch];

    float* dst = out + (long)bc * NHW;
    for (int idx = t; idx < NHW; idx += 256) {
        int y = idx >> 6, x = idx & 63;
        float acc = bb;
        #pragma unroll
        for (int ky = 0; ky < 3; ky++)
            #pragma unroll
            for (int kx = 0; kx < 3; kx++)
                acc = fmaf(wk[ky * 3 + kx], tile[y + ky][x + kx], acc);
        dst[idx] = acc;
    }
}

// row sums of px
__global__ __launch_bounds__(256) void rowsum_k(const float* __restrict__ px,
                                                float* __restrict__ r)
{
    int row = blockIdx.x * 8 + (threadIdx.x >> 5);
    int lane = threadIdx.x & 31;
    const float* p = px + (long)row * NHW;
    float s = 0.0f;
    for (int i = lane; i < NHW; i += 32) s += p[i];
    #pragma unroll
    for (int o = 16; o; o >>= 1) s += __shfl_xor_sync(0xffffffffu, s, o);
    if (lane == 0) r[row] = s;
}

// u = Wq r, w = Wk r
__global__ __launch_bounds__(256) void uw_k(
    const float* __restrict__ Wq, const float* __restrict__ Wk,
    const float* __restrict__ r, float* __restrict__ u, float* __restrict__ w)
{
    int b = blockIdx.x, t = threadIdx.x;
    __shared__ float rs[NC];
    rs[t] = r[b * NC + t];
    __syncthreads();
    float uu = 0.0f, ww = 0.0f;
    for (int c = 0; c < NC; c++) {
        float rc = rs[c];
        uu = fmaf(Wq[t * NC + c], rc, uu);
        ww = fmaf(Wk[t * NC + c], rc, ww);
    }
    u[b * NC + t] = uu;
    w[b * NC + t] = ww;
}

// softmax over rows of [B*C, C], in place
__global__ __launch_bounds__(256) void softmax_k(float* __restrict__ s)
{
    float* p = s + (long)blockIdx.x * NC;
    int t = threadIdx.x, lane = t & 31, wp = t >> 5;
    __shared__ float redm[8], reds[8];
    __shared__ float bm, bs;
    float v = p[t];
    float m = v;
    #pragma unroll
    for (int o = 16; o; o >>= 1) m = fmaxf(m, __shfl_xor_sync(0xffffffffu, m, o));
    if (lane == 0) redm[wp] = m;
    __syncthreads();
    if (t == 0) {
        float mm = redm[0];
        for (int i = 1; i < 8; i++) mm = fmaxf(mm, redm[i]);
        bm = mm;
    }
    __syncthreads();
    float e = expf(v - bm);
    float su = e;
    #pragma unroll
    for (int o = 16; o; o >>= 1) su += __shfl_xor_sync(0xffffffffu, su, o);
    if (lane == 0) reds[wp] = su;
    __syncthreads();
    if (t == 0) {
        float ss = 0.0f;
        for (int i = 0; i < 8; i++) ss += reds[i];
        bs = 1.0f / ss;
    }
    __syncthreads();
    p[t] = e * bs;
}

// cvec = Wo @ (att^T bv) + op_b
__global__ __launch_bounds__(256) void ycvec_k(
    const float* __restrict__ att, const float* __restrict__ bv,
    const float* __restrict__ Wo, const float* __restrict__ ob,
    float* __restrict__ cvec)
{
    int b = blockIdx.x, t = threadIdx.x;
    __shared__ float ys[NC];
    const float* ab = att + (long)b * NC * NC;
    float y = 0.0f;
    for (int c = 0; c < NC; c++) y = fmaf(ab[c * NC + t], bv[c], y);
    ys[t] = y;
    __syncthreads();
    float cv = 0.0f;
    for (int d = 0; d < NC; d++) cv = fmaf(Wo[t * NC + d], ys[d], cv);
    cvec[b * NC + t] = cv + ob[t];
}

// =============================================================================
extern "C" void kernel_launch(void* const* d_in, const int* in_sizes, int n_in,
                              void* d_out, int out_size)
{
    const float* z     = (const float*)d_in[0];
    const float* x     = (const float*)d_in[1];
    const float* dten  = (const float*)d_in[2];
    const float* dw_w  = (const float*)d_in[3];
    const float* dw_b  = (const float*)d_in[4];
    const float* pw_w  = (const float*)d_in[5];
    const float* pw_b  = (const float*)d_in[6];
    const float* bn_g  = (const float*)d_in[7];
    const float* bn_be = (const float*)d_in[8];
    const float* bn_m  = (const float*)d_in[9];
    const float* bn_v  = (const float*)d_in[10];
    const float* inp_w = (const float*)d_in[11];
    const float* inp_b = (const float*)d_in[12];
    const float* q_w   = (const float*)d_in[13];
    const float* q_b   = (const float*)d_in[14];
    const float* k_w   = (const float*)d_in[15];
    const float* k_b   = (const float*)d_in[16];
    const float* v_w   = (const float*)d_in[17];
    const float* v_b   = (const float*)d_in[18];
    const float* op_w  = (const float*)d_in[19];
    const float* op_b  = (const float*)d_in[20];
    float* out = (float*)d_out;

    float* base = nullptr;
    cudaGetSymbolAddress((void**)&base, g_scratch);
    float* corr = base + OFF_CORR;
    float* dwb  = base + OFF_DW;
    float* sbuf = base + OFF_S;
    float* px   = base + OFF_PX;
    float* G    = base + OFF_G;
    float* T1   = base + OFF_T1;
    float* att  = base + OFF_ATT;
    float* T2   = base + OFF_T2;
    float* Mm   = base + OFF_M;
    float* r    = base + OFF_R;
    float* u    = base + OFF_U;
    float* w    = base + OFF_W;
    float* cvec = base + OFF_CV;

    dim3 blk(256);
    const float* np = nullptr;

    // 1) correlation: corr[b] = z[b]^T (64x256) @ x[b] (256x4096)
    gemm_k<1,0,0><<<dim3(64,1,NB), blk>>>(z, x, corr, NK, NHW, NC,
        (long)NC*NK, (long)NC*NHW, (long)NK*NHW, np,np,np,np);

    // 2) depthwise 3x3 over concat(corr, d)
    dw_k<<<NB*NIN, blk>>>(corr, dten, dw_w, dw_b, dwb);

    // 3) pointwise + bias + BN + ReLU -> s
    gemm128_k<0,2,1><<<dim3(32,2,NB), blk>>>(pw_w, dwb, sbuf, NC, NHW, NIN,
        0L, (long)NIN*NHW, (long)NC*NHW, pw_b, bn_m, bn_v, bn_g, bn_be);

    // 4) px = inp_w @ s + inp_b
    gemm128_k<0,1,1><<<dim3(32,2,NB), blk>>>(inp_w, sbuf, px, NC, NHW, NC,
        0L, (long)NC*NHW, (long)NC*NHW, inp_b, np,np,np,np);

    // 5) r = px row sums
    rowsum_k<<<NB*NC/8, blk>>>(px, r);

    // 6) G[b] = px[b] @ px[b]^T  (split-K x8 with atomicAdd)
    zero_k<<<(NB*NC*NC + 1023)/1024, 1024>>>(G, (long)NB*NC*NC);
    gemm128_k<1,0,8><<<dim3(2,2,NB*8), blk>>>(px, px, G, NC, NC, NHW,
        (long)NC*NHW, (long)NC*NHW, (long)NC*NC, np,np,np,np,np);

    // 7) u = Wq r, w = Wk r
    uw_k<<<NB, blk>>>(q_w, k_w, r, u, w);

    // 8) T1 = Wq @ G
    gemm_k<0,0,0><<<dim3(4,4,NB), blk>>>(q_w, G, T1, NC, NC, NC,
        0L, (long)NC*NC, (long)NC*NC, np,np,np,np);

    // 9) score = (T1 @ Wk^T + u bk^T + bq w^T + N bq bk^T)/16
    gemm_k<0,1,3><<<dim3(4,4,NB), blk>>>(T1, k_w, att, NC, NC, NC,
        (long)NC*NC, 0L, (long)NC*NC, u, k_b, q_b, w);

    // 10) softmax rows
    softmax_k<<<NB*NC, blk>>>(att);

    // 11) cvec = Wo @ (att^T bv) + op_b
    ycvec_k<<<NB, blk>>>(att, v_b, op_w, op_b, cvec);

    // 12) T2 = att^T @ Wv
    gemm_k<1,0,0><<<dim3(4,4,NB), blk>>>(att, v_w, T2, NC, NC, NC,
        (long)NC*NC, 0L, (long)NC*NC, np,np,np,np);

    // 13) M = Wo @ T2
    gemm_k<0,0,0><<<dim3(4,4,NB), blk>>>(op_w, T2, Mm, NC, NC, NC,
        0L, (long)NC*NC, (long)NC*NC, np,np,np,np);

    // 14) out = M @ px + cvec + s
    gemm128_k<0,4,1><<<dim3(32,2,NB), blk>>>(Mm, px, out, NC, NHW, NC,
        (long)NC*NC, (long)NC*NHW, (long)NC*NHW, cvec, sbuf, np,np,np);
}

// round 4
// speedup vs baseline: 1.5448x; 1.5448x over previous
#include <cuda_runtime.h>
#include <math.h>

#define NB 32
#define NC 256
#define NK 64
#define NHW 4096
#define NIN 320
#define BN_EPS 1e-5f

// ---------------- scratch (static device global; no allocation at runtime) ----
#define OFF_CORR 0L                       // 32*64*4096
#define OFF_DW   8388608L                 // 32*320*4096
#define OFF_S    50331648L                // 32*256*4096
#define OFF_PX   83886080L                // 32*256*4096
#define OFF_G    117440512L               // 32*256*256
#define OFF_T1   119537664L
#define OFF_ATT  121634816L
#define OFF_T2   123731968L
#define OFF_M    125829120L
#define OFF_R    127926272L               // 32*256
#define OFF_U    127934464L
#define OFF_W    127942656L
#define OFF_CV   127950848L
#define SCRATCH_FLOATS 127959040L

__device__ float g_scratch[SCRATCH_FLOATS];

// ---------------- packed f32x2 helpers (ptxas will NOT auto-fuse; PTX only) --
__device__ __forceinline__ unsigned long long pack2(float lo, float hi) {
    unsigned long long r;
    asm("mov.b64 %0, {%1, %2};" : "=l"(r) : "f"(lo), "f"(hi));
    return r;
}
__device__ __forceinline__ void unpack2(unsigned long long v, float& lo, float& hi) {
    asm("mov.b64 {%0, %1}, %2;" : "=f"(lo), "=f"(hi) : "l"(v));
}
#define FFMA2(d, a, b) asm("fma.rn.f32x2 %0, %1, %2, %0;" : "+l"(d) : "l"(a), "l"(b))

// =============================================================================
// Big GEMM: 128x128 block tile, BK=8, 8x8 per thread (packed 4x8 f32x2), 256 thr.
// A row-major [M,K]. BMODE: 0 = B row-major [K,N]; 1 = B is [N,K] (B^T).
// EPI: 0 none | 1 +bias(p0[m]) | 2 bias+BN+ReLU | 4 final (+cvec +s)
// SPLIT: K-split factor; if >1 epilogue is atomicAdd (C must be zeroed first).
// =============================================================================
template<int BMODE, int EPI, int SPLIT>
__global__ __launch_bounds__(256) void gemm128_k(
    const float* __restrict__ A, const float* __restrict__ Bm, float* __restrict__ Cm,
    int M, int N, int Kd, long aBS, long bBS, long cBS,
    const float* __restrict__ p0, const float* __restrict__ p1,
    const float* __restrict__ p2, const float* __restrict__ p3,
    const float* __restrict__ p4)
{
    __shared__ float As[8][132];
    __shared__ float Bs[8][132];
    const int b  = blockIdx.z / SPLIT;
    const int ks = blockIdx.z % SPLIT;
    const int KC = Kd / SPLIT;
    const float* Ab = A  + (long)b * aBS;
    const float* Bb = Bm + (long)b * bBS;
    float* Cb = Cm + (long)b * cBS;
    const int n0 = blockIdx.x * 128;
    const int m0 = blockIdx.y * 128;
    const int t  = threadIdx.x;
    const int tx = t & 15, ty = t >> 4;

    // acc2[ih][j]: lo = row 2*ih, hi = row 2*ih+1 of the 8x8 micro-tile
    unsigned long long acc2[4][8];
    #pragma unroll
    for (int i = 0; i < 4; i++)
        #pragma unroll
        for (int j = 0; j < 8; j++) acc2[i][j] = 0ull;

    const int arow = t >> 1, akq = (t & 1) * 4;
    const int kend = (ks + 1) * KC;
    for (int k0 = ks * KC; k0 < kend; k0 += 8) {
        // ---- stage A tile: As[kk][m] ----
        {
            float4 va = *reinterpret_cast<const float4*>(&Ab[(long)(m0 + arow) * Kd + k0 + akq]);
            As[akq + 0][arow] = va.x; As[akq + 1][arow] = va.y;
            As[akq + 2][arow] = va.z; As[akq + 3][arow] = va.w;
        }
        // ---- stage B tile: Bs[kk][n] ----
        if (BMODE == 0) {
            int kk = t >> 5, nq = (t & 31) * 4;
            float4 vb = *reinterpret_cast<const float4*>(&Bb[(long)(k0 + kk) * N + n0 + nq]);
            *reinterpret_cast<float4*>(&Bs[kk][nq]) = vb;
        } else {
            int n = t >> 1, kq = (t & 1) * 4;
            float4 vb = *reinterpret_cast<const float4*>(&Bb[(long)(n0 + n) * Kd + k0 + kq]);
            Bs[kq + 0][n] = vb.x; Bs[kq + 1][n] = vb.y;
            Bs[kq + 2][n] = vb.z; Bs[kq + 3][n] = vb.w;
        }
        __syncthreads();

        #pragma unroll
        for (int kk = 0; kk < 8; kk++) {
            // A pairs come packed for free from the vector LDS
            ulonglong2 au0 = *reinterpret_cast<const ulonglong2*>(&As[kk][ty * 8]);
            ulonglong2 au1 = *reinterpret_cast<const ulonglong2*>(&As[kk][ty * 8 + 4]);
            unsigned long long au[4] = {au0.x, au0.y, au1.x, au1.y};
            float4 b0 = *reinterpret_cast<const float4*>(&Bs[kk][tx * 8]);
            float4 b1 = *reinterpret_cast<const float4*>(&Bs[kk][tx * 8 + 4]);
            unsigned long long bd[8];
            bd[0] = pack2(b0.x, b0.x); bd[1] = pack2(b0.y, b0.y);
            bd[2] = pack2(b0.z, b0.z); bd[3] = pack2(b0.w, b0.w);
            bd[4] = pack2(b1.x, b1.x); bd[5] = pack2(b1.y, b1.y);
            bd[6] = pack2(b1.z, b1.z); bd[7] = pack2(b1.w, b1.w);
            #pragma unroll
            for (int i = 0; i < 4; i++)
                #pragma unroll
                for (int j = 0; j < 8; j++)
                    FFMA2(acc2[i][j], au[i], bd[j]);
        }
        __syncthreads();
    }

    // ---- epilogue ----
    #pragma unroll
    for (int ih = 0; ih < 4; ih++) {
        float vlo[8], vhi[8];
        #pragma unroll
        for (int j = 0; j < 8; j++) unpack2(acc2[ih][j], vlo[j], vhi[j]);
        const int mlo = m0 + ty * 8 + 2 * ih;
        const int mhi = mlo + 1;
        if (SPLIT > 1) {
            #pragma unroll
            for (int j = 0; j < 8; j++) {
                int n = n0 + tx * 8 + j;
                atomicAdd(&Cb[(long)mlo * N + n], vlo[j]);
                atomicAdd(&Cb[(long)mhi * N + n], vhi[j]);
            }
        } else {
            #pragma unroll
            for (int half = 0; half < 2; half++) {
                const int m = half ? mhi : mlo;
                float* vv = half ? vhi : vlo;
                if (EPI == 1) {
                    float bias = p0[m];
                    #pragma unroll
                    for (int j = 0; j < 8; j++) vv[j] += bias;
                } else if (EPI == 2) {
                    float bias  = p0[m];
                    float scale = rsqrtf(p2[m] + BN_EPS) * p3[m];
                    float mean  = p1[m], beta = p4[m];
                    #pragma unroll
                    for (int j = 0; j < 8; j++) {
                        float xx = vv[j] + bias;
                        xx = (xx - mean) * scale + beta;
                        vv[j] = fmaxf(xx, 0.0f);
                    }
                } else if (EPI == 4) {
                    float cv = p0[b * NC + m];
                    const float* srow = &p1[(long)b * cBS + (long)m * N + n0 + tx * 8];
                    float4 s0 = *reinterpret_cast<const float4*>(srow);
                    float4 s1 = *reinterpret_cast<const float4*>(srow + 4);
                    vv[0] += cv + s0.x; vv[1] += cv + s0.y;
                    vv[2] += cv + s0.z; vv[3] += cv + s0.w;
                    vv[4] += cv + s1.x; vv[5] += cv + s1.y;
                    vv[6] += cv + s1.z; vv[7] += cv + s1.w;
                }
                *reinterpret_cast<float4*>(&Cb[(long)m * N + n0 + tx * 8]) =
                    make_float4(vv[0], vv[1], vv[2], vv[3]);
                *reinterpret_cast<float4*>(&Cb[(long)m * N + n0 + tx * 8 + 4]) =
                    make_float4(vv[4], vv[5], vv[6], vv[7]);
            }
        }
    }
}

__global__ void zero_k(float* __restrict__ p, long n)
{
    long i = (long)blockIdx.x * blockDim.x + threadIdx.x;
    if (i < n) p[i] = 0.0f;
}

// =============================================================================
// Small GEMM: 64x64 tile, 4x4/thread (packed 2x4 f32x2)
// AM: 0 = A row-major [M,K]; 1 = A^T.  BM: 0 = B row-major; 1 = B^T.
// EPI: 0 none | 3 score epilogue
// =============================================================================
template<int AM, int BM, int EPI>
__global__ __launch_bounds__(256) void gemm_k(
    const float* __restrict__ A, const float* __restrict__ Bm, float* __restrict__ Cm,
    int M, int N, int Kd, long aBS, long bBS, long cBS,
    const float* __restrict__ p0, const float* __restrict__ p1,
    const float* __restrict__ p2, const float* __restrict__ p3)
{
    __shared__ float As[16][64];
    __shared__ float Bs[16][64];
    const int b = blockIdx.z;
    const float* Ab = A + (long)b * aBS;
    const float* Bb = Bm + (long)b * bBS;
    float* Cb = Cm + (long)b * cBS;
    const int n0 = blockIdx.x * 64;
    const int m0 = blockIdx.y * 64;
    const int t  = threadIdx.x;
    const int tx = t & 15, ty = t >> 4;

    unsigned long long acc2[2][4];
    #pragma unroll
    for (int i = 0; i < 2; i++)
        #pragma unroll
        for (int j = 0; j < 4; j++) acc2[i][j] = 0ull;

    for (int k0 = 0; k0 < Kd; k0 += 16) {
        if (AM == 0) {
            int m = t >> 2, kq = (t & 3) * 4;
            float4 va = *reinterpret_cast<const float4*>(&Ab[(long)(m0 + m) * Kd + k0 + kq]);
            As[kq + 0][m] = va.x; As[kq + 1][m] = va.y;
            As[kq + 2][m] = va.z; As[kq + 3][m] = va.w;
        } else {
            int kk = t >> 4, mq = (t & 15) * 4;
            float4 va = *reinterpret_cast<const float4*>(&Ab[(long)(k0 + kk) * M + m0 + mq]);
            *reinterpret_cast<float4*>(&As[kk][mq]) = va;
        }
        if (BM == 0) {
            int kk = t >> 4, nq = (t & 15) * 4;
            float4 vb = *reinterpret_cast<const float4*>(&Bb[(long)(k0 + kk) * N + n0 + nq]);
            *reinterpret_cast<float4*>(&Bs[kk][nq]) = vb;
        } else {
            int n = t >> 2, kq = (t & 3) * 4;
            float4 vb = *reinterpret_cast<const float4*>(&Bb[(long)(n0 + n) * Kd + k0 + kq]);
            Bs[kq + 0][n] = vb.x; Bs[kq + 1][n] = vb.y;
            Bs[kq + 2][n] = vb.z; Bs[kq + 3][n] = vb.w;
        }
        __syncthreads();

        #pragma unroll
        for (int kk = 0; kk < 16; kk++) {
            ulonglong2 auv = *reinterpret_cast<const ulonglong2*>(&As[kk][ty * 4]);
            unsigned long long au[2] = {auv.x, auv.y};
            float4 bf = *reinterpret_cast<const float4*>(&Bs[kk][tx * 4]);
            unsigned long long bd[4];
            bd[0] = pack2(bf.x, bf.x); bd[1] = pack2(bf.y, bf.y);
            bd[2] = pack2(bf.z, bf.z); bd[3] = pack2(bf.w, bf.w);
            #pragma unroll
            for (int i = 0; i < 2; i++)
                #pragma unroll
                for (int j = 0; j < 4; j++)
                    FFMA2(acc2[i][j], au[i], bd[j]);
        }
        __syncthreads();
    }

    #pragma unroll
    for (int ih = 0; ih < 2; ih++) {
        float vlo[4], vhi[4];
        #pragma unroll
        for (int j = 0; j < 4; j++) unpack2(acc2[ih][j], vlo[j], vhi[j]);
        #pragma unroll
        for (int half = 0; half < 2; half++) {
            const int m = m0 + ty * 4 + 2 * ih + half;
            float* vv = half ? vhi : vlo;
            if (EPI == 3) {
                float u  = p0[b * NC + m];
                float bq = p2[m];
                #pragma unroll
                for (int j = 0; j < 4; j++) {
                    int n = n0 + tx * 4 + j;
                    float bk = p1[n];
                    float w  = p3[b * NC + n];
                    vv[j] = (vv[j] + u * bk + bq * w + 4096.0f * bq * bk) * 0.0625f;
                }
            }
            *reinterpret_cast<float4*>(&Cb[(long)m * N + n0 + tx * 4]) =
                make_float4(vv[0], vv[1], vv[2], vv[3]);
        }
    }
}

// =============================================================================
// Depthwise 3x3 (pad 1) over concat([corr(64ch), d(256ch)])
// =============================================================================
__global__ __launch_bounds__(256) void dw_k(
    const float* __restrict__ corr, const float* __restrict__ dten,
    const float* __restrict__ w, const float* __restrict__ bias,
    float* __restrict__ out)
{
    const int bc = blockIdx.x;
    const int b = bc / NIN, ch = bc % NIN;
    const float* src = (ch < NK) ? (corr + ((long)b * NK + ch) * NHW)
                                 : (dten + ((long)b * NC + (ch - NK)) * NHW);
    __shared__ float tile[66][66];
    const int t = threadIdx.x;
    for (int idx = t; idx < 66 * 66; idx += 256) {
        int yy = idx / 66, xx = idx % 66;
        int y = yy - 1, x = xx - 1;
        float v = 0.0f;
        if (y >= 0 && y < 64 && x >= 0 && x < 64) v = src[y * 64 + x];
        tile[yy][xx] = v;
    }
    __syncthreads();

    float wk[9];
    #pragma unroll
    for (int i = 0; i < 9; i++) wk[i] = w[ch * 9 + i];
    const float bb = bias[ch];

    float* dst = out + (long)bc * NHW;
    for (int idx = t; idx < NHW; idx += 256) {
        int y = idx >> 6, x = idx & 63;
        float acc = bb;
        #pragma unroll
        for (int ky = 0; ky < 3; ky++)
            #pragma unroll
            for (int kx = 0; kx < 3; kx++)
                acc = fmaf(wk[ky * 3 + kx], tile[y + ky][x + kx], acc);
        dst[idx] = acc;
    }
}

// row sums of px
__global__ __launch_bounds__(256) void rowsum_k(const float* __restrict__ px,
                                                float* __restrict__ r)
{
    int row = blockIdx.x * 8 + (threadIdx.x >> 5);
    int lane = threadIdx.x & 31;
    const float* p = px + (long)row * NHW;
    float s = 0.0f;
    for (int i = lane; i < NHW; i += 32) s += p[i];
    #pragma unroll
    for (int o = 16; o; o >>= 1) s += __shfl_xor_sync(0xffffffffu, s, o);
    if (lane == 0) r[row] = s;
}

// u = Wq r, w = Wk r
__global__ __launch_bounds__(256) void uw_k(
    const float* __restrict__ Wq, const float* __restrict__ Wk,
    const float* __restrict__ r, float* __restrict__ u, float* __restrict__ w)
{
    int b = blockIdx.x, t = threadIdx.x;
    __shared__ float rs[NC];
    rs[t] = r[b * NC + t];
    __syncthreads();
    float uu = 0.0f, ww = 0.0f;
    for (int c = 0; c < NC; c++) {
        float rc = rs[c];
        uu = fmaf(Wq[t * NC + c], rc, uu);
        ww = fmaf(Wk[t * NC + c], rc, ww);
    }
    u[b * NC + t] = uu;
    w[b * NC + t] = ww;
}

// softmax over rows of [B*C, C], in place
__global__ __launch_bounds__(256) void softmax_k(float* __restrict__ s)
{
    float* p = s + (long)blockIdx.x * NC;
    int t = threadIdx.x, lane = t & 31, wp = t >> 5;
    __shared__ float redm[8], reds[8];
    __shared__ float bm, bs;
    float v = p[t];
    float m = v;
    #pragma unroll
    for (int o = 16; o; o >>= 1) m = fmaxf(m, __shfl_xor_sync(0xffffffffu, m, o));
    if (lane == 0) redm[wp] = m;
    __syncthreads();
    if (t == 0) {
        float mm = redm[0];
        for (int i = 1; i < 8; i++) mm = fmaxf(mm, redm[i]);
        bm = mm;
    }
    __syncthreads();
    float e = expf(v - bm);
    float su = e;
    #pragma unroll
    for (int o = 16; o; o >>= 1) su += __shfl_xor_sync(0xffffffffu, su, o);
    if (lane == 0) reds[wp] = su;
    __syncthreads();
    if (t == 0) {
        float ss = 0.0f;
        for (int i = 0; i < 8; i++) ss += reds[i];
        bs = 1.0f / ss;
    }
    __syncthreads();
    p[t] = e * bs;
}

// cvec = Wo @ (att^T bv) + op_b
__global__ __launch_bounds__(256) void ycvec_k(
    const float* __restrict__ att, const float* __restrict__ bv,
    const float* __restrict__ Wo, const float* __restrict__ ob,
    float* __restrict__ cvec)
{
    int b = blockIdx.x, t = threadIdx.x;
    __shared__ float ys[NC];
    const float* ab = att + (long)b * NC * NC;
    float y = 0.0f;
    for (int c = 0; c < NC; c++) y = fmaf(ab[c * NC + t], bv[c], y);
    ys[t] = y;
    __syncthreads();
    float cv = 0.0f;
    for (int d = 0; d < NC; d++) cv = fmaf(Wo[t * NC + d], ys[d], cv);
    cvec[b * NC + t] = cv + ob[t];
}

// =============================================================================
extern "C" void kernel_launch(void* const* d_in, const int* in_sizes, int n_in,
                              void* d_out, int out_size)
{
    const float* z     = (const float*)d_in[0];
    const float* x     = (const float*)d_in[1];
    const float* dten  = (const float*)d_in[2];
    const float* dw_w  = (const float*)d_in[3];
    const float* dw_b  = (const float*)d_in[4];
    const float* pw_w  = (const float*)d_in[5];
    const float* pw_b  = (const float*)d_in[6];
    const float* bn_g  = (const float*)d_in[7];
    const float* bn_be = (const float*)d_in[8];
    const float* bn_m  = (const float*)d_in[9];
    const float* bn_v  = (const float*)d_in[10];
    const float* inp_w = (const float*)d_in[11];
    const float* inp_b = (const float*)d_in[12];
    const float* q_w   = (const float*)d_in[13];
    const float* q_b   = (const float*)d_in[14];
    const float* k_w   = (const float*)d_in[15];
    const float* k_b   = (const float*)d_in[16];
    const float* v_w   = (const float*)d_in[17];
    const float* v_b   = (const float*)d_in[18];
    const float* op_w  = (const float*)d_in[19];
    const float* op_b  = (const float*)d_in[20];
    float* out = (float*)d_out;

    float* base = nullptr;
    cudaGetSymbolAddress((void**)&base, g_scratch);
    float* corr = base + OFF_CORR;
    float* dwb  = base + OFF_DW;
    float* sbuf = base + OFF_S;
    float* px   = base + OFF_PX;
    float* G    = base + OFF_G;
    float* T1   = base + OFF_T1;
    float* att  = base + OFF_ATT;
    float* T2   = base + OFF_T2;
    float* Mm   = base + OFF_M;
    float* r    = base + OFF_R;
    float* u    = base + OFF_U;
    float* w    = base + OFF_W;
    float* cvec = base + OFF_CV;

    dim3 blk(256);
    const float* np = nullptr;

    // 1) correlation: corr[b] = z[b]^T (64x256) @ x[b] (256x4096)
    gemm_k<1,0,0><<<dim3(64,1,NB), blk>>>(z, x, corr, NK, NHW, NC,
        (long)NC*NK, (long)NC*NHW, (long)NK*NHW, np,np,np,np);

    // 2) depthwise 3x3 over concat(corr, d)
    dw_k<<<NB*NIN, blk>>>(corr, dten, dw_w, dw_b, dwb);

    // 3) pointwise + bias + BN + ReLU -> s
    gemm128_k<0,2,1><<<dim3(32,2,NB), blk>>>(pw_w, dwb, sbuf, NC, NHW, NIN,
        0L, (long)NIN*NHW, (long)NC*NHW, pw_b, bn_m, bn_v, bn_g, bn_be);

    // 4) px = inp_w @ s + inp_b
    gemm128_k<0,1,1><<<dim3(32,2,NB), blk>>>(inp_w, sbuf, px, NC, NHW, NC,
        0L, (long)NC*NHW, (long)NC*NHW, inp_b, np,np,np,np);

    // 5) r = px row sums
    rowsum_k<<<NB*NC/8, blk>>>(px, r);

    // 6) G[b] = px[b] @ px[b]^T  (split-K x8 with atomicAdd)
    zero_k<<<(NB*NC*NC + 1023)/1024, 1024>>>(G, (long)NB*NC*NC);
    gemm128_k<1,0,8><<<dim3(2,2,NB*8), blk>>>(px, px, G, NC, NC, NHW,
        (long)NC*NHW, (long)NC*NHW, (long)NC*NC, np,np,np,np,np);

    // 7) u = Wq r, w = Wk r
    uw_k<<<NB, blk>>>(q_w, k_w, r, u, w);

    // 8) T1 = Wq @ G
    gemm_k<0,0,0><<<dim3(4,4,NB), blk>>>(q_w, G, T1, NC, NC, NC,
        0L, (long)NC*NC, (long)NC*NC, np,np,np,np);

    // 9) score = (T1 @ Wk^T + u bk^T + bq w^T + N bq bk^T)/16
    gemm_k<0,1,3><<<dim3(4,4,NB), blk>>>(T1, k_w, att, NC, NC, NC,
        (long)NC*NC, 0L, (long)NC*NC, u, k_b, q_b, w);

    // 10) softmax rows
    softmax_k<<<NB*NC, blk>>>(att);

    // 11) cvec = Wo @ (att^T bv) + op_b
    ycvec_k<<<NB, blk>>>(att, v_b, op_w, op_b, cvec);

    // 12) T2 = att^T @ Wv
    gemm_k<1,0,0><<<dim3(4,4,NB), blk>>>(att, v_w, T2, NC, NC, NC,
        (long)NC*NC, 0L, (long)NC*NC, np,np,np,np);

    // 13) M = Wo @ T2
    gemm_k<0,0,0><<<dim3(4,4,NB), blk>>>(op_w, T2, Mm, NC, NC, NC,
        0L, (long)NC*NC, (long)NC*NC, np,np,np,np);

    // 14) out = M @ px + cvec + s
    gemm128_k<0,4,1><<<dim3(32,2,NB), blk>>>(Mm, px, out, NC, NHW, NC,
        (long)NC*NC, (long)NC*NHW, (long)NC*NHW, cvec, sbuf, np,np,np);
}